// round 8
// baseline (speedup 1.0000x reference)
#include <cuda_runtime.h>
#include <cstdint>
#include <math.h>

#define BATCH 16
#define CIN 512
#define COUT 512
#define WDIM 512
#define MTOT 4608      // 9 * 512
#define NTOT 16384     // 16 * 1024

// ------------------------- static scratch (no allocs) -----------------------
__device__ float g_style[BATCH * CIN];
__device__ float g_dcoef[BATCH * COUT];
__device__ float g_wsq[COUT * CIN];
__device__ float g_A[MTOT * 512];          // A[(k*512+co)][ci], tf32-rounded
__device__ float g_B[NTOT * 512];          // B[(b*1024+p)][ci], tf32-rounded
__device__ float g_z[(size_t)MTOT * NTOT]; // z[(k,co)][(b,p)] fp32

// ------------------------------ helpers -------------------------------------
static __device__ __forceinline__ uint32_t smem_u32(const void* p) {
    uint32_t a;
    asm("{ .reg .u64 t; cvta.to.shared.u64 t, %1; cvt.u32.u64 %0, t; }"
        : "=r"(a) : "l"(p));
    return a;
}
static __device__ __forceinline__ float to_tf32(float v) {
    uint32_t t;
    asm("cvt.rna.tf32.f32 %0, %1;" : "=r"(t) : "f"(v));
    return __uint_as_float(t);
}

// ---------------------------------------------------------------------------
// prep kernels
// ---------------------------------------------------------------------------
__global__ void style_kernel(const float* __restrict__ wl,
                             const float* __restrict__ aw,
                             const float* __restrict__ ab) {
    int b = blockIdx.x, ci = threadIdx.x;
    __shared__ float sw[WDIM];
    sw[ci] = wl[b * WDIM + ci];
    __syncthreads();
    const float* row = aw + (size_t)ci * WDIM;
    float acc = 0.f;
#pragma unroll 8
    for (int k = 0; k < WDIM; k++) acc += sw[k] * row[k];
    g_style[b * CIN + ci] = acc * 0.04419417382415922f + ab[ci];
}

__global__ void dcoef_kernel() {
    int b = blockIdx.x, co = threadIdx.x;
    __shared__ float s2[CIN];
    float st = g_style[b * CIN + co];
    s2[co] = st * st;
    __syncthreads();
    const float* row = g_wsq + (size_t)co * CIN;
    float acc = 0.f;
#pragma unroll 8
    for (int ci = 0; ci < CIN; ci++) acc += s2[ci] * row[ci];
    g_dcoef[b * COUT + co] = rsqrtf(acc + 1e-8f);
}

// Fused: A[(k*512+co)][ci] = tf32(cw[co][ci][k]), wsq[co][ci] = sum_k cw^2
// Block = (co, 128-wide ci slab): coalesced read of 1152 floats, staged in smem.
__global__ __launch_bounds__(256) void pack_a_wsq_kernel(const float* __restrict__ cw) {
    __shared__ float s[1152];
    const int co = blockIdx.x >> 2;
    const int ci0 = (blockIdx.x & 3) << 7;
    const float* src = cw + ((size_t)co * 512 + ci0) * 9;
    for (int i = threadIdx.x; i < 1152; i += 256) s[i] = src[i];
    __syncthreads();
    for (int i = threadIdx.x; i < 1152; i += 256) {
        int k = i >> 7, cil = i & 127;
        g_A[((size_t)(k * 512 + co)) * 512 + ci0 + cil] = to_tf32(s[cil * 9 + k]);
    }
    if (threadIdx.x < 128) {
        float acc = 0.f;
#pragma unroll
        for (int k = 0; k < 9; k++) { float v = s[threadIdx.x * 9 + k]; acc += v * v; }
        g_wsq[(size_t)co * 512 + ci0 + threadIdx.x] = acc;
    }
}

// B[(b*1024+p)][ci] = x[b][ci][p] * style[b][ci]   (32x128 smem transpose)
__global__ __launch_bounds__(256) void btpack_kernel(const float* __restrict__ x) {
    const int ct = blockIdx.x;  // ci tile (16 of 32)
    const int pt = blockIdx.y;  // p tile (8 of 128)
    const int b = blockIdx.z;
    __shared__ float sm[32][129];
    const int tid = threadIdx.x;
    const int pl = tid & 127, c0 = tid >> 7;
    const float* xb = x + ((size_t)b * 512 + ct * 32) * 1024 + pt * 128;
    const float* stb = g_style + b * 512 + ct * 32;
#pragma unroll
    for (int cl = c0; cl < 32; cl += 2)
        sm[cl][pl] = xb[(size_t)cl * 1024 + pl] * stb[cl];
    __syncthreads();
    const int cl2 = tid & 31, p2b = tid >> 5;
    float* ob = g_B + ((size_t)b * 1024 + pt * 128) * 512 + ct * 32;
#pragma unroll
    for (int pp = p2b; pp < 128; pp += 8)
        ob[(size_t)pp * 512 + cl2] = to_tf32(sm[cl2][pp]);
}

// ---------------------------------------------------------------------------
// GEMM via mma.sync tf32. z[m][n] = sum_ci A[m][ci] * B[n][ci].
// CTA tile 128x128, BK=16 double-buffered cp.async.
// 4 warps (128 thr) as 2(M) x 2(N); warp tile 64x64; mma m16n8k8.
// smem rows padded to 20 floats (80B) -> conflict-free LDSM.
// grid.x = M tiles (36): a wave shares the 9MB A matrix (L2-resident) and
// streams few B tiles -> B read ~once from DRAM.
// ---------------------------------------------------------------------------
#define BK 16
#define LDP 20  // padded row length in floats

__global__ __launch_bounds__(128, 2) void gemm_kernel() {
    __shared__ float As[2][128 * LDP];
    __shared__ float Bs[2][128 * LDP];

    const int tid = threadIdx.x;
    const int wid = tid >> 5, lane = tid & 31;
    const int m0g = blockIdx.x * 128, n0g = blockIdx.y * 128;
    const int m0w = (wid & 1) * 64, n0w = (wid >> 1) * 64;

    const float* Ag = g_A + (size_t)m0g * 512;
    const float* Bg = g_B + (size_t)n0g * 512;

    const uint32_t sA0 = smem_u32(&As[0][0]);
    const uint32_t sB0 = smem_u32(&Bs[0][0]);
    const uint32_t bufstride = 128 * LDP * 4;

#define ISSUE_STAGE(st, buf) do {                                              \
    int kb = (st) * BK;                                                        \
    _Pragma("unroll")                                                          \
    for (int i = 0; i < 4; i++) {                                              \
        int chunk = tid + i * 128;                                             \
        int r = chunk >> 2, ch = chunk & 3;                                    \
        uint32_t doff = (uint32_t)(r * LDP + ch * 4) * 4 + (buf) * bufstride;  \
        asm volatile("cp.async.cg.shared.global [%0], [%1], 16;"               \
                     :: "r"(sA0 + doff), "l"(Ag + (size_t)r * 512 + kb + ch * 4) : "memory"); \
        asm volatile("cp.async.cg.shared.global [%0], [%1], 16;"               \
                     :: "r"(sB0 + doff), "l"(Bg + (size_t)r * 512 + kb + ch * 4) : "memory"); \
    }                                                                          \
    asm volatile("cp.async.commit_group;" ::: "memory");                       \
} while (0)

    float acc[4][8][4];
#pragma unroll
    for (int a = 0; a < 4; a++)
#pragma unroll
        for (int b = 0; b < 8; b++)
#pragma unroll
            for (int c = 0; c < 4; c++) acc[a][b][c] = 0.f;

    // ldmatrix.x4 lane mapping (16-row group, two k-quadrants) — same for A & B
    const int grow = ((lane >> 3) & 1) * 8 + (lane & 7);
    const int gcol = ((lane >> 4) & 1) * 4;

    ISSUE_STAGE(0, 0);
    ISSUE_STAGE(1, 1);

    const int NSTAGE = 512 / BK;  // 32
#pragma unroll 1
    for (int kt = 0; kt < NSTAGE; kt++) {
        const int buf = kt & 1;
        if (kt == NSTAGE - 1)
            asm volatile("cp.async.wait_group 0;" ::: "memory");
        else
            asm volatile("cp.async.wait_group 1;" ::: "memory");
        __syncthreads();

        const uint32_t smA = sA0 + buf * bufstride;
        const uint32_t smB = sB0 + buf * bufstride;

#pragma unroll
        for (int s = 0; s < 2; s++) {
            const int k0 = s * 8;
            uint32_t a[4][4];   // mf: 16 rows x 8k
            uint32_t b[4][4];   // pair p: 16 n-rows x 8k (nf=2p,2p+1)
#pragma unroll
            for (int mf = 0; mf < 4; mf++) {
                uint32_t addr = smA +
                    (uint32_t)((m0w + mf * 16 + grow) * LDP + k0 + gcol) * 4;
                asm volatile(
                    "ldmatrix.sync.aligned.m8n8.x4.shared.b16 {%0,%1,%2,%3}, [%4];"
                    : "=r"(a[mf][0]), "=r"(a[mf][1]), "=r"(a[mf][2]), "=r"(a[mf][3])
                    : "r"(addr));
            }
#pragma unroll
            for (int p = 0; p < 4; p++) {
                uint32_t addr = smB +
                    (uint32_t)((n0w + p * 16 + grow) * LDP + k0 + gcol) * 4;
                asm volatile(
                    "ldmatrix.sync.aligned.m8n8.x4.shared.b16 {%0,%1,%2,%3}, [%4];"
                    : "=r"(b[p][0]), "=r"(b[p][1]), "=r"(b[p][2]), "=r"(b[p][3])
                    : "r"(addr));
            }
            // regs: b[p][0]=(n0-7,k0-3) b[p][1]=(n8-15,k0-3)
            //       b[p][2]=(n0-7,k4-7) b[p][3]=(n8-15,k4-7)
#pragma unroll
            for (int mf = 0; mf < 4; mf++)
#pragma unroll
                for (int p = 0; p < 4; p++) {
                    asm volatile(
                        "mma.sync.aligned.m16n8k8.row.col.f32.tf32.tf32.f32 "
                        "{%0,%1,%2,%3}, {%4,%5,%6,%7}, {%8,%9}, {%0,%1,%2,%3};"
                        : "+f"(acc[mf][2 * p][0]), "+f"(acc[mf][2 * p][1]),
                          "+f"(acc[mf][2 * p][2]), "+f"(acc[mf][2 * p][3])
                        : "r"(a[mf][0]), "r"(a[mf][1]), "r"(a[mf][2]), "r"(a[mf][3]),
                          "r"(b[p][0]), "r"(b[p][2]));
                    asm volatile(
                        "mma.sync.aligned.m16n8k8.row.col.f32.tf32.tf32.f32 "
                        "{%0,%1,%2,%3}, {%4,%5,%6,%7}, {%8,%9}, {%0,%1,%2,%3};"
                        : "+f"(acc[mf][2 * p + 1][0]), "+f"(acc[mf][2 * p + 1][1]),
                          "+f"(acc[mf][2 * p + 1][2]), "+f"(acc[mf][2 * p + 1][3])
                        : "r"(a[mf][0]), "r"(a[mf][1]), "r"(a[mf][2]), "r"(a[mf][3]),
                          "r"(b[p][1]), "r"(b[p][3]));
                }
        }
        __syncthreads();
        if (kt + 2 < NSTAGE) ISSUE_STAGE(kt + 2, buf);
    }

    // epilogue: store accumulators to g_z
    float* zbase = g_z + (size_t)(m0g + m0w) * NTOT + (n0g + n0w);
    const int rq = lane >> 2, cq = lane & 3;
#pragma unroll
    for (int mf = 0; mf < 4; mf++)
#pragma unroll
        for (int nf = 0; nf < 8; nf++) {
            float* p0 = zbase + (size_t)(mf * 16 + rq) * NTOT + nf * 8 + 2 * cq;
            *(float2*)p0 = make_float2(acc[mf][nf][0], acc[mf][nf][1]);
            float* p1 = p0 + (size_t)8 * NTOT;
            *(float2*)p1 = make_float2(acc[mf][nf][2], acc[mf][nf][3]);
        }
}

// ---------------------------------------------------------------------------
// assemble: scatter 9 z planes -> y (65x65), demod, FIR, noise/bias/act/clamp
// ---------------------------------------------------------------------------
__global__ __launch_bounds__(256) void assemble_kernel(
    const float* __restrict__ noise, const float* __restrict__ nstr,
    const float* __restrict__ bias, float* __restrict__ out) {
    const int co = blockIdx.x, b = blockIdx.y;
    const int tid = threadIdx.x;
    __shared__ float yp[67][68];
    for (int i = tid; i < 67 * 68; i += 256) ((float*)yp)[i] = 0.f;
    __syncthreads();

#pragma unroll 1
    for (int k = 0; k < 9; k++) {
        const float* zp = g_z + ((size_t)(k * 512 + co)) * NTOT + b * 1024;
        float4 v = ((const float4*)zp)[tid];
        int p = tid * 4;
        int i = p >> 5, j = p & 31;
        int row = 2 * i + 1 + k / 3;
        int col = 2 * j + 1 + (k % 3);
        yp[row][col] += v.x;
        yp[row][col + 2] += v.y;
        yp[row][col + 4] += v.z;
        yp[row][col + 6] += v.w;
        __syncthreads();
    }

    const float dc = g_dcoef[b * COUT + co];
    const float nst = nstr[0];
    const float bc = bias[co];
    const float* nzb = noise + (size_t)b * 4096;
    float* ob = out + (((size_t)b * COUT + co) << 12);
    const float fw0 = 0.25f, fw1 = 0.75f;

#pragma unroll 4
    for (int jj = 0; jj < 16; jj++) {
        int px = tid + 256 * jj;
        int u = px >> 6, v = px & 63;
        float sum = 0.f;
#pragma unroll
        for (int a = 0; a < 4; a++) {
            float fa = (a == 0 || a == 3) ? fw0 : fw1;
            float rs = fw0 * yp[u + a][v] + fw1 * yp[u + a][v + 1] +
                       fw1 * yp[u + a][v + 2] + fw0 * yp[u + a][v + 3];
            sum += fa * rs;
        }
        float val = sum * dc + nzb[px] * nst + bc;
        val = (val > 0.f) ? val : 0.2f * val;
        val *= 1.4142135623730951f;
        val = fminf(fmaxf(val, -256.f), 256.f);
        ob[px] = val;
    }
}

// ---------------------------------------------------------------------------
// launch: 0:x 1:w_latent 2:affine_weight 3:affine_bias 4:conv_weight
//         5:noise 6:noise_strength 7:bias
// ---------------------------------------------------------------------------
extern "C" void kernel_launch(void* const* d_in, const int* in_sizes, int n_in,
                              void* d_out, int out_size) {
    const float* x = (const float*)d_in[0];
    const float* wl = (const float*)d_in[1];
    const float* aw = (const float*)d_in[2];
    const float* ab = (const float*)d_in[3];
    const float* cw = (const float*)d_in[4];
    const float* nz = (const float*)d_in[5];
    const float* ns = (const float*)d_in[6];
    const float* bs = (const float*)d_in[7];
    float* out = (float*)d_out;

    style_kernel<<<BATCH, 512>>>(wl, aw, ab);
    pack_a_wsq_kernel<<<COUT * 4, 256>>>(cw);
    dcoef_kernel<<<BATCH, 512>>>();
    btpack_kernel<<<dim3(16, 8, BATCH), 256>>>(x);
    gemm_kernel<<<dim3(MTOT / 128, NTOT / 128), 128>>>();
    assemble_kernel<<<dim3(COUT, BATCH), 256>>>(nz, ns, bs, out);
}